// round 4
// baseline (speedup 1.0000x reference)
#include <cuda_runtime.h>
#include <cstdint>

// ---------------------------------------------------------------------------
// WindowAttention (Swin-style), GB300 sm_103a — fully fused single kernel.
// Per block (one window, 512 threads):
//   Phase 1: QKV GEMM  (gathered rolled x rows @ w_qkv, tf32 mma)
//   Phase B: S = Q K^T * scale + rel-pos bias (+ boundary masks)
//   Phase C: softmax (register, shfl)
//   Phase D/E: P @ V
//   Phase F/G: fused output projection @ w_out + bias, un-roll scatter
// No global scratch round-trip: Q/K/V live only in smem.
// ---------------------------------------------------------------------------

__device__ uint32_t g_wqkv_tf[128 * 384];
__device__ uint32_t g_wout_tf[128 * 128];

__device__ __forceinline__ uint32_t f2tf(float f) {
    uint32_t r;
    asm("cvt.rna.tf32.f32 %0, %1;" : "=r"(r) : "f"(f));
    return r;
}
__device__ __forceinline__ uint32_t saddr(const void* p) {
    return (uint32_t)__cvta_generic_to_shared(p);
}
#define CP16(dst, src) \
    asm volatile("cp.async.cg.shared.global [%0], [%1], 16;\n" :: "r"(dst), "l"(src))
#define CP_COMMIT() asm volatile("cp.async.commit_group;\n")

__device__ __forceinline__ void mma8(float* c, const uint32_t* a, const uint32_t* b) {
    asm volatile(
        "mma.sync.aligned.m16n8k8.row.col.f32.tf32.tf32.f32 "
        "{%0,%1,%2,%3}, {%4,%5,%6,%7}, {%8,%9}, {%0,%1,%2,%3};\n"
        : "+f"(c[0]), "+f"(c[1]), "+f"(c[2]), "+f"(c[3])
        : "r"(a[0]), "r"(a[1]), "r"(a[2]), "r"(a[3]), "r"(b[0]), "r"(b[1]));
}

// ===========================================================================
// K0: weight conversion fp32 -> tf32 bits
// ===========================================================================
__global__ void cvt_kernel(const float* __restrict__ wqkv,
                           const float* __restrict__ wout) {
    int i = blockIdx.x * 256 + threadIdx.x;
    if (i < 128 * 384) g_wqkv_tf[i] = f2tf(wqkv[i]);
    if (i < 128 * 128) g_wout_tf[i] = f2tf(wout[i]);
}

// ===========================================================================
// Fused kernel.  smem layout (uint32 elements):
//   sQ : [0     , 8448 )   64x132          (phase G: sW overlays sQ+sK)
//   sK : [8448  , 16896)   64x132
//   sV : [16896 , 25344)   64x132          (phase F/G: sO overlays)
//   sA : [25344 , 33792)   64x132  GEMM A  (later: sP region)
//   sB : [33792 , 42240)   2x32x132 GEMM B (later: sP region)
//   sP : [25344 , 42752)   4 heads x 64x68 (overlays sA+sB)
//   PE : [42752 , 43008)
//   BO : [43008 , 43136)
// ===========================================================================
#define SQ_OFF 0
#define SK_OFF 8448
#define SV_OFF 16896
#define SA_OFF 25344
#define SB_OFF 33792
#define SP_OFF 25344
#define PE_OFF 42752
#define BO_OFF 43008
#define FU_ELEMS 43136
#define FU_SMEM (FU_ELEMS * 4)    // 172544 B

__global__ __launch_bounds__(512, 1)
void fused_kernel(const float* __restrict__ x,
                  const float* __restrict__ bout,
                  const float* __restrict__ pe,  const float* __restrict__ ul,
                  const float* __restrict__ lr,  float* __restrict__ out) {
    extern __shared__ uint32_t sm[];
    uint32_t* sQ = sm + SQ_OFF;
    uint32_t* sK = sm + SK_OFF;
    uint32_t* sV = sm + SV_OFF;
    uint32_t* sA = sm + SA_OFF;
    uint32_t* sB = sm + SB_OFF;
    uint32_t* sP = sm + SP_OFF;
    uint32_t* sO = sm + SV_OFF;     // overlays sV (dead after phase E)
    uint32_t* sW = sm + SQ_OFF;     // overlays sQ+sK (dead after phase B)
    float* sPE = (float*)(sm + PE_OFF);
    float* sBO = (float*)(sm + BO_OFF);

    const int t = threadIdx.x;
    const int warp = t >> 5, lane = t & 31;
    const int gid = lane >> 2, tid4 = lane & 3;
    const int blk = blockIdx.x;
    const int bb = blk >> 8, win = blk & 255;
    const int wy = win >> 4, wx = win & 15;

    // ---- Phase 1a: issue first B tile, gather A (rolled x rows, tf32) ----
    auto issueB = [&](int tileIdx) {
        const int nb = tileIdx >> 2, kt = tileIdx & 3, buf = tileIdx & 1;
        uint32_t* dstB = sB + buf * (32 * 132);
        #pragma unroll
        for (int jj = 0; jj < 2; jj++) {
            int i = t + 512 * jj;
            int rowb = i >> 5, c16 = i & 31;
            CP16(saddr(dstB + rowb * 132 + c16 * 4),
                 g_wqkv_tf + (kt * 32 + rowb) * 384 + nb * 128 + c16 * 4);
        }
        CP_COMMIT();
    };
    issueB(0);

    {
        const int row_a = t >> 3, part = t & 7;    // 64 rows x 8 parts of 16
        const int ty = row_a >> 3, tx = row_a & 7;
        const int sh = (wy * 8 + ty + 4) & 127, sw = (wx * 8 + tx + 4) & 127;
        const float* aptr = x + (((size_t)bb * 128 + sh) * 128 + sw) * 128 + part * 16;
        uint32_t* ap = sA + row_a * 132 + part * 16;
        #pragma unroll
        for (int j = 0; j < 4; j++) {
            float4 v = *(const float4*)(aptr + j * 4);
            ap[j * 4 + 0] = f2tf(v.x); ap[j * 4 + 1] = f2tf(v.y);
            ap[j * 4 + 2] = f2tf(v.z); ap[j * 4 + 3] = f2tf(v.w);
        }
    }
    if (t < 225) sPE[t] = pe[t];
    if (t < 128) sBO[t] = bout[t];

    // ---- Phase 1b: QKV GEMM, 3 segments (Q,K,V) x 4 k-chunks of 32 ----
    // Warp grid 2 (M) x 8 (N): warp tile 32 rows x 16 cols.
    const int gwm = warp & 1, gwn = warp >> 1;

    for (int nb = 0; nb < 3; nb++) {
        float acc[2][2][4];
        #pragma unroll
        for (int a = 0; a < 2; a++)
            #pragma unroll
            for (int b2 = 0; b2 < 2; b2++)
                #pragma unroll
                for (int c = 0; c < 4; c++) acc[a][b2][c] = 0.f;

        for (int kt = 0; kt < 4; kt++) {
            const int cur = nb * 4 + kt;
            if (cur + 1 < 12) {
                issueB(cur + 1);
                asm volatile("cp.async.wait_group 1;\n");
            } else {
                asm volatile("cp.async.wait_group 0;\n");
            }
            __syncthreads();

            const uint32_t* Bm = sB + (cur & 1) * (32 * 132);
            #pragma unroll
            for (int kk = 0; kk < 32; kk += 8) {
                uint32_t af[2][4], bf[2][2];
                #pragma unroll
                for (int mt = 0; mt < 2; mt++) {
                    int row = gwm * 32 + mt * 16 + gid;
                    int kc = kt * 32 + kk + tid4;
                    af[mt][0] = sA[row * 132 + kc];
                    af[mt][1] = sA[(row + 8) * 132 + kc];
                    af[mt][2] = sA[row * 132 + kc + 4];
                    af[mt][3] = sA[(row + 8) * 132 + kc + 4];
                }
                #pragma unroll
                for (int nt = 0; nt < 2; nt++) {
                    int col = gwn * 16 + nt * 8 + gid;
                    bf[nt][0] = Bm[(kk + tid4) * 132 + col];
                    bf[nt][1] = Bm[(kk + tid4 + 4) * 132 + col];
                }
                #pragma unroll
                for (int mt = 0; mt < 2; mt++)
                    #pragma unroll
                    for (int nt = 0; nt < 2; nt++)
                        mma8(acc[mt][nt], af[mt], bf[nt]);
            }
            __syncthreads();   // protect buffer before tile cur+2 lands
        }

        // write segment result (tf32) into sQ / sK / sV
        uint32_t* dst = (nb == 0) ? sQ : (nb == 1) ? sK : sV;
        #pragma unroll
        for (int mt = 0; mt < 2; mt++) {
            int row = gwm * 32 + mt * 16 + gid;
            #pragma unroll
            for (int nt = 0; nt < 2; nt++) {
                int col = gwn * 16 + nt * 8 + tid4 * 2;
                dst[row * 132 + col]           = f2tf(acc[mt][nt][0]);
                dst[row * 132 + col + 1]       = f2tf(acc[mt][nt][1]);
                dst[(row + 8) * 132 + col]     = f2tf(acc[mt][nt][2]);
                dst[(row + 8) * 132 + col + 1] = f2tf(acc[mt][nt][3]);
            }
        }
    }
    __syncthreads();   // Q/K/V visible to all

    // ---- Phase B: S = Q K^T (per head; 4 warps/head, 16 rows each) ----
    const int head = warp >> 2;
    const int wrb = (warp & 3) * 16;
    const int hoff = head * 32;
    float sacc[8][4];
    #pragma unroll
    for (int b2 = 0; b2 < 8; b2++)
        #pragma unroll
        for (int c = 0; c < 4; c++) sacc[b2][c] = 0.f;

    #pragma unroll
    for (int kk = 0; kk < 32; kk += 8) {
        uint32_t af[4], bf[8][2];
        {
            int row = wrb + gid;
            af[0] = sQ[row * 132 + hoff + kk + tid4];
            af[1] = sQ[(row + 8) * 132 + hoff + kk + tid4];
            af[2] = sQ[row * 132 + hoff + kk + tid4 + 4];
            af[3] = sQ[(row + 8) * 132 + hoff + kk + tid4 + 4];
        }
        #pragma unroll
        for (int nt = 0; nt < 8; nt++) {
            int key = nt * 8 + gid;
            bf[nt][0] = sK[key * 132 + hoff + kk + tid4];
            bf[nt][1] = sK[key * 132 + hoff + kk + tid4 + 4];
        }
        #pragma unroll
        for (int nt = 0; nt < 8; nt++)
            mma8(sacc[nt], af, bf[nt]);
    }

    // ---- Phase C: bias + masks + softmax ----
    const float scale = 0.17677669529663689f;
    const bool addUL = (wy == 15);
    const bool addLR = (wx == 15);

    #pragma unroll
    for (int rh = 0; rh < 2; rh++) {
        const int i = wrb + rh * 8 + gid;
        const int iy = i >> 3, ix = i & 7;
        float vrow[16];
        float m = -1e30f;
        #pragma unroll
        for (int nt = 0; nt < 8; nt++) {
            #pragma unroll
            for (int u = 0; u < 2; u++) {
                int j = nt * 8 + tid4 * 2 + u;
                int jy = j >> 3, jx = j & 7;
                float v = sacc[nt][rh * 2 + u] * scale
                        + sPE[(jy - iy + 7) * 15 + (jx - ix + 7)];
                if (addUL) v += ul[i * 64 + j];
                if (addLR) v += lr[i * 64 + j];
                vrow[nt * 2 + u] = v;
                m = fmaxf(m, v);
            }
        }
        m = fmaxf(m, __shfl_xor_sync(0xffffffffu, m, 1));
        m = fmaxf(m, __shfl_xor_sync(0xffffffffu, m, 2));
        float sum = 0.f;
        #pragma unroll
        for (int u2 = 0; u2 < 16; u2++) {
            vrow[u2] = __expf(vrow[u2] - m);
            sum += vrow[u2];
        }
        sum += __shfl_xor_sync(0xffffffffu, sum, 1);
        sum += __shfl_xor_sync(0xffffffffu, sum, 2);
        float inv = 1.f / sum;
        #pragma unroll
        for (int nt = 0; nt < 8; nt++) {
            #pragma unroll
            for (int u = 0; u < 2; u++)
                sacc[nt][rh * 2 + u] = vrow[nt * 2 + u] * inv;
        }
    }
    __syncthreads();   // all warps done reading sQ/sK

    // ---- issue w_out prefetch into sW (overlays sQ+sK) ----
    #pragma unroll
    for (int jj = 0; jj < 8; jj++) {
        int i = t + 512 * jj;
        int row = i >> 5, c16 = i & 31;
        CP16(saddr(sW + row * 132 + c16 * 4), g_wout_tf + row * 128 + c16 * 4);
    }
    CP_COMMIT();

    // ---- Phase D: store P (tf32) into sP[head] ----
    uint32_t* myP = sP + head * (64 * 68);
    #pragma unroll
    for (int rh = 0; rh < 2; rh++) {
        int i = wrb + rh * 8 + gid;
        #pragma unroll
        for (int nt = 0; nt < 8; nt++) {
            int j = nt * 8 + tid4 * 2;
            myP[i * 68 + j]     = f2tf(sacc[nt][rh * 2]);
            myP[i * 68 + j + 1] = f2tf(sacc[nt][rh * 2 + 1]);
        }
    }
    __syncthreads();

    // ---- Phase E: O = P @ V (warp: 16 rows x 32 head-dims) ----
    float oacc[4][4];
    #pragma unroll
    for (int b2 = 0; b2 < 4; b2++)
        #pragma unroll
        for (int c = 0; c < 4; c++) oacc[b2][c] = 0.f;

    #pragma unroll
    for (int kk = 0; kk < 64; kk += 8) {
        uint32_t af[4], bf[4][2];
        {
            int row = wrb + gid;
            af[0] = myP[row * 68 + kk + tid4];
            af[1] = myP[(row + 8) * 68 + kk + tid4];
            af[2] = myP[row * 68 + kk + tid4 + 4];
            af[3] = myP[(row + 8) * 68 + kk + tid4 + 4];
        }
        #pragma unroll
        for (int nt = 0; nt < 4; nt++) {
            int d = nt * 8 + gid;
            bf[nt][0] = sV[(kk + tid4) * 132 + hoff + d];
            bf[nt][1] = sV[(kk + tid4 + 4) * 132 + hoff + d];
        }
        #pragma unroll
        for (int nt = 0; nt < 4; nt++)
            mma8(oacc[nt], af, bf[nt]);
    }
    __syncthreads();   // done reading sV and sP

    // ---- Phase F: store O (tf32) to sO [token][128] (overlays sV) ----
    #pragma unroll
    for (int nt = 0; nt < 4; nt++) {
        int i = wrb + gid;
        int c = hoff + nt * 8 + tid4 * 2;
        sO[i * 132 + c]           = f2tf(oacc[nt][0]);
        sO[i * 132 + c + 1]       = f2tf(oacc[nt][1]);
        sO[(i + 8) * 132 + c]     = f2tf(oacc[nt][2]);
        sO[(i + 8) * 132 + c + 1] = f2tf(oacc[nt][3]);
    }
    asm volatile("cp.async.wait_group 0;\n");
    __syncthreads();

    // ---- Phase G: Y = O @ w_out + b_out, un-roll scatter ----
    // Warp grid 4 (M) x 4 (N): warp tile 16 rows x 32 cols.
    const int pwm = warp & 3, pwn = warp >> 2;
    float yacc[4][4];
    #pragma unroll
    for (int b2 = 0; b2 < 4; b2++)
        #pragma unroll
        for (int c = 0; c < 4; c++) yacc[b2][c] = 0.f;

    #pragma unroll
    for (int kk = 0; kk < 128; kk += 8) {
        uint32_t af[4], bf[4][2];
        {
            int row = pwm * 16 + gid;
            af[0] = sO[row * 132 + kk + tid4];
            af[1] = sO[(row + 8) * 132 + kk + tid4];
            af[2] = sO[row * 132 + kk + tid4 + 4];
            af[3] = sO[(row + 8) * 132 + kk + tid4 + 4];
        }
        #pragma unroll
        for (int nt = 0; nt < 4; nt++) {
            int col = pwn * 32 + nt * 8 + gid;
            bf[nt][0] = sW[(kk + tid4) * 132 + col];
            bf[nt][1] = sW[(kk + tid4 + 4) * 132 + col];
        }
        #pragma unroll
        for (int nt = 0; nt < 4; nt++)
            mma8(yacc[nt], af, bf[nt]);
    }

    #pragma unroll
    for (int rh = 0; rh < 2; rh++) {
        int i = pwm * 16 + rh * 8 + gid;
        int ty = i >> 3, tx = i & 7;
        int h = (wy * 8 + ty + 4) & 127;
        int w = (wx * 8 + tx + 4) & 127;
        float* orow = out + (((size_t)bb * 128 + h) * 128 + w) * 128;
        #pragma unroll
        for (int nt = 0; nt < 4; nt++) {
            int c = pwn * 32 + nt * 8 + tid4 * 2;
            float2 v = make_float2(yacc[nt][rh * 2]     + sBO[c],
                                   yacc[nt][rh * 2 + 1] + sBO[c + 1]);
            *(float2*)(orow + c) = v;
        }
    }
}

// ===========================================================================
extern "C" void kernel_launch(void* const* d_in, const int* in_sizes, int n_in,
                              void* d_out, int out_size) {
    const float* x    = (const float*)d_in[0];
    const float* wqkv = (const float*)d_in[1];
    const float* wout = (const float*)d_in[2];
    const float* bout = (const float*)d_in[3];
    const float* pe   = (const float*)d_in[4];
    const float* ul   = (const float*)d_in[5];
    const float* lr   = (const float*)d_in[6];
    float* out = (float*)d_out;

    cudaFuncSetAttribute(fused_kernel, cudaFuncAttributeMaxDynamicSharedMemorySize, FU_SMEM);

    cvt_kernel<<<192, 256>>>(wqkv, wout);
    fused_kernel<<<4096, 512, FU_SMEM>>>(x, bout, pe, ul, lr, out);
}

// round 5
// speedup vs baseline: 1.3023x; 1.3023x over previous
#include <cuda_runtime.h>
#include <cstdint>

// ---------------------------------------------------------------------------
// WindowAttention (Swin-style), GB300 sm_103a — fused, k-paired smem layouts.
// cvt: w_qkv -> w_qkv^T paired tf32; w_out -> w_out^T paired tf32.
// fused (1 block / window, 512 thr):
//   P1: QKV = A(rolled x, paired) @ w_qkvT  (single pass N=384, cp.async 2-buf)
//   PB: S = Q K^T + bias(+masks); PC: softmax; PE: P@V; PG: proj + un-roll.
// All mma fragment loads are LDS.64 via pair-interleaved k-groups.
// ---------------------------------------------------------------------------

__device__ uint32_t g_wqkvT[384 * 128];   // [n][k-paired]
__device__ uint32_t g_woutT[128 * 128];   // [n][k-paired]

__device__ __forceinline__ uint32_t f2tf(float f) {
    uint32_t r;
    asm("cvt.rna.tf32.f32 %0, %1;" : "=r"(r) : "f"(f));
    return r;
}
__device__ __forceinline__ uint32_t saddr(const void* p) {
    return (uint32_t)__cvta_generic_to_shared(p);
}
#define CP16(dst, src) \
    asm volatile("cp.async.cg.shared.global [%0], [%1], 16;\n" :: "r"(dst), "l"(src))
#define CP_COMMIT() asm volatile("cp.async.commit_group;\n")

__device__ __forceinline__ void mma8(float* c, const uint32_t* a, const uint32_t* b) {
    asm volatile(
        "mma.sync.aligned.m16n8k8.row.col.f32.tf32.tf32.f32 "
        "{%0,%1,%2,%3}, {%4,%5,%6,%7}, {%8,%9}, {%0,%1,%2,%3};\n"
        : "+f"(c[0]), "+f"(c[1]), "+f"(c[2]), "+f"(c[3])
        : "r"(a[0]), "r"(a[1]), "r"(a[2]), "r"(a[3]), "r"(b[0]), "r"(b[1]));
}
// slot within an 8-wide k-group: [k0 k4 k1 k5 k2 k6 k3 k7]
__device__ __forceinline__ int SL(int c) { return ((c & 3) << 1) | (c >> 2); }

// ===========================================================================
// cvt: transpose + pair + tf32-convert weights
// ===========================================================================
__global__ void cvt_kernel(const float* __restrict__ wqkv,
                           const float* __restrict__ wout) {
    int i = blockIdx.x * 256 + threadIdx.x;
    if (i < 384 * 128) {
        int n = i >> 7, kp = i & 127;
        int g = kp >> 3, s = kp & 7;
        int k = g * 8 + (s >> 1) + ((s & 1) << 2);
        g_wqkvT[i] = f2tf(wqkv[k * 384 + n]);
    }
    if (i < 128 * 128) {
        int n = i >> 7, kp = i & 127;
        int g = kp >> 3, s = kp & 7;
        int k = g * 8 + (s >> 1) + ((s & 1) << 2);
        g_woutT[i] = f2tf(wout[k * 128 + n]);
    }
}

// ===========================================================================
// smem map (u32):
//  sQ 0..8704   sK 8704..17408   sV 17408..26112   (stride 136, k/d-paired)
//  sA 26112..34816 (stride 136, paired)
//  sB 34816..53248 (2 x [384][24] k=16 tiles)
//  sP 26112..44544 (4 heads x [64][72], overlays sA+sB)
//  sW 0..17408     ([128 n][136], overlays sQ+sK)
//  sO 17408..26112 (overlays sV)
//  PE 53248  BO 53504   total 53632 u32 = 214528 B
// ===========================================================================
#define SQ_OFF 0
#define SK_OFF 8704
#define SV_OFF 17408
#define SA_OFF 26112
#define SB_OFF 34816
#define SP_OFF 26112
#define PE_OFF 53248
#define BO_OFF 53504
#define FU_SMEM (53632 * 4)

__global__ __launch_bounds__(512, 1)
void fused_kernel(const float* __restrict__ x,
                  const float* __restrict__ bout,
                  const float* __restrict__ pe,  const float* __restrict__ ul,
                  const float* __restrict__ lr,  float* __restrict__ out) {
    extern __shared__ uint32_t sm[];
    uint32_t* sQ = sm + SQ_OFF;
    uint32_t* sK = sm + SK_OFF;
    uint32_t* sV = sm + SV_OFF;
    uint32_t* sA = sm + SA_OFF;
    uint32_t* sB = sm + SB_OFF;
    uint32_t* sP = sm + SP_OFF;
    uint32_t* sW = sm + SQ_OFF;
    uint32_t* sO = sm + SV_OFF;
    float* sPE = (float*)(sm + PE_OFF);
    float* sBO = (float*)(sm + BO_OFF);

    const int t = threadIdx.x;
    const int warp = t >> 5, lane = t & 31;
    const int gid = lane >> 2, tid4 = lane & 3;
    const int blk = blockIdx.x;
    const int bb = blk >> 8, win = blk & 255;
    const int wy = win >> 4, wx = win & 15;

    // ---- B-tile loader: [384 n][16 k-cols paired] for k-chunk kt ----
    auto issueB = [&](int kt, int buf) {
        uint32_t* dst = sB + buf * 9216;
        #pragma unroll
        for (int jj = 0; jj < 3; jj++) {
            int i = t + 512 * jj;
            int n = i >> 2, cc = i & 3;
            CP16(saddr(dst + n * 24 + cc * 4),
                 g_wqkvT + n * 128 + kt * 16 + cc * 4);
        }
        CP_COMMIT();
    };
    issueB(0, 0);
    issueB(1, 1);

    // ---- A gather: rolled x rows, tf32, pair-interleaved ----
    {
        const int row_a = t >> 3, part = t & 7;
        const int ty = row_a >> 3, tx = row_a & 7;
        const int sh = (wy * 8 + ty + 4) & 127, sw = (wx * 8 + tx + 4) & 127;
        const float* aptr = x + (((size_t)bb * 128 + sh) * 128 + sw) * 128 + part * 16;
        uint32_t* ap = sA + row_a * 136;
        #pragma unroll
        for (int j4 = 0; j4 < 4; j4++) {
            float4 v = *(const float4*)(aptr + j4 * 4);
            int grp = part * 2 + (j4 >> 1);
            int odd = (j4 & 1);
            ap[grp * 8 + 0 + odd] = f2tf(v.x);
            ap[grp * 8 + 2 + odd] = f2tf(v.y);
            ap[grp * 8 + 4 + odd] = f2tf(v.z);
            ap[grp * 8 + 6 + odd] = f2tf(v.w);
        }
    }
    if (t < 225) sPE[t] = pe[t];
    if (t < 128) sBO[t] = bout[t];

    // ---- Phase 1: QKV GEMM, warp tile 32 x 48, 8 k-chunks of 16 ----
    const int gwm = warp & 1, gwn = warp >> 1;
    const int rowb1 = gwm * 32, colb1 = gwn * 48;
    float acc[2][6][4];
    #pragma unroll
    for (int a = 0; a < 2; a++)
        #pragma unroll
        for (int b2 = 0; b2 < 6; b2++)
            #pragma unroll
            for (int c = 0; c < 4; c++) acc[a][b2][c] = 0.f;

    for (int kt = 0; kt < 8; kt++) {
        if (kt < 7) asm volatile("cp.async.wait_group 1;\n");
        else        asm volatile("cp.async.wait_group 0;\n");
        __syncthreads();
        const uint32_t* Bm = sB + (kt & 1) * 9216;
        #pragma unroll
        for (int kk = 0; kk < 2; kk++) {
            uint2 afp[2][2];
            #pragma unroll
            for (int mt = 0; mt < 2; mt++) {
                int row = rowb1 + mt * 16 + gid;
                int ka = kt * 16 + kk * 8 + 2 * tid4;
                afp[mt][0] = *(const uint2*)&sA[row * 136 + ka];
                afp[mt][1] = *(const uint2*)&sA[(row + 8) * 136 + ka];
            }
            uint2 bfp[6];
            #pragma unroll
            for (int nt = 0; nt < 6; nt++) {
                int n = colb1 + nt * 8 + gid;
                bfp[nt] = *(const uint2*)&Bm[n * 24 + kk * 8 + 2 * tid4];
            }
            #pragma unroll
            for (int mt = 0; mt < 2; mt++) {
                uint32_t a[4] = {afp[mt][0].x, afp[mt][1].x, afp[mt][0].y, afp[mt][1].y};
                #pragma unroll
                for (int nt = 0; nt < 6; nt++)
                    mma8(acc[mt][nt], a, (const uint32_t*)&bfp[nt]);
            }
        }
        __syncthreads();
        if (kt + 2 < 8) issueB(kt + 2, kt & 1);
    }

    // epilogue: write Q/K/V (tf32, paired) into sQ/sK/sV
    {
        const int s0 = SL(2 * tid4), s1 = SL(2 * tid4 + 1);
        #pragma unroll
        for (int mt = 0; mt < 2; mt++) {
            int r0 = rowb1 + mt * 16 + gid, r1 = r0 + 8;
            #pragma unroll
            for (int nt = 0; nt < 6; nt++) {
                int gcol = colb1 + nt * 8;
                int seg = gcol >> 7, loc = gcol & 127;
                uint32_t* dst = sm + (seg == 0 ? SQ_OFF : seg == 1 ? SK_OFF : SV_OFF) + loc;
                dst[r0 * 136 + s0] = f2tf(acc[mt][nt][0]);
                dst[r0 * 136 + s1] = f2tf(acc[mt][nt][1]);
                dst[r1 * 136 + s0] = f2tf(acc[mt][nt][2]);
                dst[r1 * 136 + s1] = f2tf(acc[mt][nt][3]);
            }
        }
    }
    __syncthreads();

    // ---- Phase B: S = Q K^T (4 warps/head, 16 q-rows each) ----
    const int head = warp >> 2;
    const int wrb = (warp & 3) * 16;
    const int hoff = head * 32;
    float sacc[8][4];
    #pragma unroll
    for (int b2 = 0; b2 < 8; b2++)
        #pragma unroll
        for (int c = 0; c < 4; c++) sacc[b2][c] = 0.f;

    #pragma unroll
    for (int kk = 0; kk < 32; kk += 8) {
        uint2 a0 = *(const uint2*)&sQ[(wrb + gid) * 136 + hoff + kk + 2 * tid4];
        uint2 a1 = *(const uint2*)&sQ[(wrb + 8 + gid) * 136 + hoff + kk + 2 * tid4];
        uint32_t a[4] = {a0.x, a1.x, a0.y, a1.y};
        #pragma unroll
        for (int nt = 0; nt < 8; nt++) {
            int key = nt * 8 + gid;
            uint2 b = *(const uint2*)&sK[key * 136 + hoff + kk + 2 * tid4];
            mma8(sacc[nt], a, (const uint32_t*)&b);
        }
    }

    // ---- Phase C: bias + masks + softmax ----
    const float scale = 0.17677669529663689f;
    const bool addUL = (wy == 15);
    const bool addLR = (wx == 15);

    #pragma unroll
    for (int rh = 0; rh < 2; rh++) {
        const int i = wrb + rh * 8 + gid;
        const int iy = i >> 3, ix = i & 7;
        float vrow[16];
        float m = -1e30f;
        #pragma unroll
        for (int nt = 0; nt < 8; nt++) {
            #pragma unroll
            for (int u = 0; u < 2; u++) {
                int j = nt * 8 + tid4 * 2 + u;
                int jy = j >> 3, jx = j & 7;
                float v = sacc[nt][rh * 2 + u] * scale
                        + sPE[(jy - iy + 7) * 15 + (jx - ix + 7)];
                if (addUL) v += ul[i * 64 + j];
                if (addLR) v += lr[i * 64 + j];
                vrow[nt * 2 + u] = v;
                m = fmaxf(m, v);
            }
        }
        m = fmaxf(m, __shfl_xor_sync(0xffffffffu, m, 1));
        m = fmaxf(m, __shfl_xor_sync(0xffffffffu, m, 2));
        float sum = 0.f;
        #pragma unroll
        for (int u2 = 0; u2 < 16; u2++) {
            vrow[u2] = __expf(vrow[u2] - m);
            sum += vrow[u2];
        }
        sum += __shfl_xor_sync(0xffffffffu, sum, 1);
        sum += __shfl_xor_sync(0xffffffffu, sum, 2);
        float inv = 1.f / sum;
        #pragma unroll
        for (int nt = 0; nt < 8; nt++) {
            #pragma unroll
            for (int u = 0; u < 2; u++)
                sacc[nt][rh * 2 + u] = vrow[nt * 2 + u] * inv;
        }
    }
    __syncthreads();   // all warps past S reads of sQ/sK

    // ---- prefetch w_outT into sW (overlays sQ+sK) ----
    #pragma unroll
    for (int jj = 0; jj < 8; jj++) {
        int i = t + 512 * jj;
        int row = i >> 5, cc = i & 31;
        CP16(saddr(sW + row * 136 + cc * 4), g_woutT + row * 128 + cc * 4);
    }
    CP_COMMIT();

    // ---- Phase D: store P (tf32, token-paired) ----
    uint32_t* myP = sP + head * (64 * 72);
    {
        const int s0 = SL(2 * tid4), s1 = SL(2 * tid4 + 1);
        #pragma unroll
        for (int rh = 0; rh < 2; rh++) {
            int i = wrb + rh * 8 + gid;
            #pragma unroll
            for (int nt = 0; nt < 8; nt++) {
                myP[i * 72 + nt * 8 + s0] = f2tf(sacc[nt][rh * 2]);
                myP[i * 72 + nt * 8 + s1] = f2tf(sacc[nt][rh * 2 + 1]);
            }
        }
    }
    __syncthreads();

    // ---- Phase E: O = P @ V ----
    float oacc[4][4];
    #pragma unroll
    for (int b2 = 0; b2 < 4; b2++)
        #pragma unroll
        for (int c = 0; c < 4; c++) oacc[b2][c] = 0.f;
    const int dslot = SL(gid);

    #pragma unroll
    for (int kk = 0; kk < 8; kk++) {
        uint2 a0 = *(const uint2*)&myP[(wrb + gid) * 72 + kk * 8 + 2 * tid4];
        uint2 a1 = *(const uint2*)&myP[(wrb + 8 + gid) * 72 + kk * 8 + 2 * tid4];
        uint32_t a[4] = {a0.x, a1.x, a0.y, a1.y};
        #pragma unroll
        for (int nt = 0; nt < 4; nt++) {
            int dcol = hoff + nt * 8 + dslot;
            uint32_t b[2];
            b[0] = sV[(kk * 8 + tid4) * 136 + dcol];
            b[1] = sV[(kk * 8 + tid4 + 4) * 136 + dcol];
            mma8(oacc[nt], a, b);
        }
    }
    __syncthreads();   // done reading sV, sP

    // ---- Phase F: store O (tf32, paired) into sO (overlays sV) ----
    {
        const int s0 = SL(2 * tid4), s1 = SL(2 * tid4 + 1);
        #pragma unroll
        for (int nt = 0; nt < 4; nt++) {
            int grp = hoff + nt * 8;
            sO[(wrb + gid) * 136 + grp + s0]     = f2tf(oacc[nt][0]);
            sO[(wrb + gid) * 136 + grp + s1]     = f2tf(oacc[nt][1]);
            sO[(wrb + 8 + gid) * 136 + grp + s0] = f2tf(oacc[nt][2]);
            sO[(wrb + 8 + gid) * 136 + grp + s1] = f2tf(oacc[nt][3]);
        }
    }
    asm volatile("cp.async.wait_group 0;\n");
    __syncthreads();

    // ---- Phase G: Y = O @ w_out + b_out, un-roll scatter ----
    const int pwm = warp & 3, pwn = warp >> 2;
    float yacc[4][4];
    #pragma unroll
    for (int b2 = 0; b2 < 4; b2++)
        #pragma unroll
        for (int c = 0; c < 4; c++) yacc[b2][c] = 0.f;

    #pragma unroll
    for (int kk = 0; kk < 16; kk++) {
        uint2 a0 = *(const uint2*)&sO[(pwm * 16 + gid) * 136 + kk * 8 + 2 * tid4];
        uint2 a1 = *(const uint2*)&sO[(pwm * 16 + 8 + gid) * 136 + kk * 8 + 2 * tid4];
        uint32_t a[4] = {a0.x, a1.x, a0.y, a1.y};
        #pragma unroll
        for (int nt = 0; nt < 4; nt++) {
            int n = pwn * 32 + nt * 8 + gid;
            uint2 b = *(const uint2*)&sW[n * 136 + kk * 8 + 2 * tid4];
            mma8(yacc[nt], a, (const uint32_t*)&b);
        }
    }

    #pragma unroll
    for (int rh = 0; rh < 2; rh++) {
        int i = pwm * 16 + rh * 8 + gid;
        int ty = i >> 3, tx = i & 7;
        int h = (wy * 8 + ty + 4) & 127;
        int w = (wx * 8 + tx + 4) & 127;
        float* orow = out + (((size_t)bb * 128 + h) * 128 + w) * 128;
        #pragma unroll
        for (int nt = 0; nt < 4; nt++) {
            int c = pwn * 32 + nt * 8 + tid4 * 2;
            float2 v = make_float2(yacc[nt][rh * 2]     + sBO[c],
                                   yacc[nt][rh * 2 + 1] + sBO[c + 1]);
            *(float2*)(orow + c) = v;
        }
    }
}

// ===========================================================================
extern "C" void kernel_launch(void* const* d_in, const int* in_sizes, int n_in,
                              void* d_out, int out_size) {
    const float* x    = (const float*)d_in[0];
    const float* wqkv = (const float*)d_in[1];
    const float* wout = (const float*)d_in[2];
    const float* bout = (const float*)d_in[3];
    const float* pe   = (const float*)d_in[4];
    const float* ul   = (const float*)d_in[5];
    const float* lr   = (const float*)d_in[6];
    float* out = (float*)d_out;

    cudaFuncSetAttribute(fused_kernel, cudaFuncAttributeMaxDynamicSharedMemorySize, FU_SMEM);

    cvt_kernel<<<192, 256>>>(wqkv, wout);
    fused_kernel<<<4096, 512, FU_SMEM>>>(x, bout, pe, ul, lr, out);
}

// round 6
// speedup vs baseline: 1.3031x; 1.0006x over previous
#include <cuda_runtime.h>
#include <cstdint>

// ---------------------------------------------------------------------------
// WindowAttention (Swin-style), GB300 sm_103a — fused, k-paired smem layouts.
// cvt: w_qkv -> w_qkv^T paired tf32; w_out -> w_out^T paired tf32.
// fused (1 block / window, 512 thr):
//   P1: QKV = A(rolled x, paired) @ w_qkvT  (single pass N=384, cp.async 2-buf)
//   PB: S = Q K^T + bias(+masks); PC: softmax; PE: P@V; PG: proj + un-roll.
// All mma fragment loads are LDS.64 via pair-interleaved k-groups.
// ---------------------------------------------------------------------------

__device__ uint32_t g_wqkvT[384 * 128];   // [n][k-paired]
__device__ uint32_t g_woutT[128 * 128];   // [n][k-paired]

__device__ __forceinline__ uint32_t f2tf(float f) {
    uint32_t r;
    asm("cvt.rna.tf32.f32 %0, %1;" : "=r"(r) : "f"(f));
    return r;
}
__device__ __forceinline__ uint32_t saddr(const void* p) {
    return (uint32_t)__cvta_generic_to_shared(p);
}
#define CP16(dst, src) \
    asm volatile("cp.async.cg.shared.global [%0], [%1], 16;\n" :: "r"(dst), "l"(src))
#define CP_COMMIT() asm volatile("cp.async.commit_group;\n")

__device__ __forceinline__ void mma8(float* c, const uint32_t* a, const uint32_t* b) {
    asm volatile(
        "mma.sync.aligned.m16n8k8.row.col.f32.tf32.tf32.f32 "
        "{%0,%1,%2,%3}, {%4,%5,%6,%7}, {%8,%9}, {%0,%1,%2,%3};\n"
        : "+f"(c[0]), "+f"(c[1]), "+f"(c[2]), "+f"(c[3])
        : "r"(a[0]), "r"(a[1]), "r"(a[2]), "r"(a[3]), "r"(b[0]), "r"(b[1]));
}
// slot within an 8-wide k-group: [k0 k4 k1 k5 k2 k6 k3 k7]
__device__ __forceinline__ int SL(int c) { return ((c & 3) << 1) | (c >> 2); }

// ===========================================================================
// cvt: transpose + pair + tf32-convert weights
// ===========================================================================
__global__ void cvt_kernel(const float* __restrict__ wqkv,
                           const float* __restrict__ wout) {
    int i = blockIdx.x * 256 + threadIdx.x;
    if (i < 384 * 128) {
        int n = i >> 7, kp = i & 127;
        int g = kp >> 3, s = kp & 7;
        int k = g * 8 + (s >> 1) + ((s & 1) << 2);
        g_wqkvT[i] = f2tf(wqkv[k * 384 + n]);
    }
    if (i < 128 * 128) {
        int n = i >> 7, kp = i & 127;
        int g = kp >> 3, s = kp & 7;
        int k = g * 8 + (s >> 1) + ((s & 1) << 2);
        g_woutT[i] = f2tf(wout[k * 128 + n]);
    }
}

// ===========================================================================
// smem map (u32):
//  sQ 0..8704   sK 8704..17408   sV 17408..26112   (stride 136, k/d-paired)
//  sA 26112..34816 (stride 136, paired)
//  sB 34816..53248 (2 x [384][24] k=16 tiles)
//  sP 26112..44544 (4 heads x [64][72], overlays sA+sB)
//  sW 0..17408     ([128 n][136], overlays sQ+sK)
//  sO 17408..26112 (overlays sV)
//  PE 53248  BO 53504   total 53632 u32 = 214528 B
// ===========================================================================
#define SQ_OFF 0
#define SK_OFF 8704
#define SV_OFF 17408
#define SA_OFF 26112
#define SB_OFF 34816
#define SP_OFF 26112
#define PE_OFF 53248
#define BO_OFF 53504
#define FU_SMEM (53632 * 4)

__global__ __launch_bounds__(512, 1)
void fused_kernel(const float* __restrict__ x,
                  const float* __restrict__ bout,
                  const float* __restrict__ pe,  const float* __restrict__ ul,
                  const float* __restrict__ lr,  float* __restrict__ out) {
    extern __shared__ uint32_t sm[];
    uint32_t* sQ = sm + SQ_OFF;
    uint32_t* sK = sm + SK_OFF;
    uint32_t* sV = sm + SV_OFF;
    uint32_t* sA = sm + SA_OFF;
    uint32_t* sB = sm + SB_OFF;
    uint32_t* sP = sm + SP_OFF;
    uint32_t* sW = sm + SQ_OFF;
    uint32_t* sO = sm + SV_OFF;
    float* sPE = (float*)(sm + PE_OFF);
    float* sBO = (float*)(sm + BO_OFF);

    const int t = threadIdx.x;
    const int warp = t >> 5, lane = t & 31;
    const int gid = lane >> 2, tid4 = lane & 3;
    const int blk = blockIdx.x;
    const int bb = blk >> 8, win = blk & 255;
    const int wy = win >> 4, wx = win & 15;

    // ---- B-tile loader: [384 n][16 k-cols paired] for k-chunk kt ----
    auto issueB = [&](int kt, int buf) {
        uint32_t* dst = sB + buf * 9216;
        #pragma unroll
        for (int jj = 0; jj < 3; jj++) {
            int i = t + 512 * jj;
            int n = i >> 2, cc = i & 3;
            CP16(saddr(dst + n * 24 + cc * 4),
                 g_wqkvT + n * 128 + kt * 16 + cc * 4);
        }
        CP_COMMIT();
    };
    issueB(0, 0);
    issueB(1, 1);

    // ---- A gather: rolled x rows, tf32, pair-interleaved ----
    {
        const int row_a = t >> 3, part = t & 7;
        const int ty = row_a >> 3, tx = row_a & 7;
        const int sh = (wy * 8 + ty + 4) & 127, sw = (wx * 8 + tx + 4) & 127;
        const float* aptr = x + (((size_t)bb * 128 + sh) * 128 + sw) * 128 + part * 16;
        uint32_t* ap = sA + row_a * 136;
        #pragma unroll
        for (int j4 = 0; j4 < 4; j4++) {
            float4 v = *(const float4*)(aptr + j4 * 4);
            int grp = part * 2 + (j4 >> 1);
            int odd = (j4 & 1);
            ap[grp * 8 + 0 + odd] = f2tf(v.x);
            ap[grp * 8 + 2 + odd] = f2tf(v.y);
            ap[grp * 8 + 4 + odd] = f2tf(v.z);
            ap[grp * 8 + 6 + odd] = f2tf(v.w);
        }
    }
    if (t < 225) sPE[t] = pe[t];
    if (t < 128) sBO[t] = bout[t];

    // ---- Phase 1: QKV GEMM, warp tile 32 x 48, 8 k-chunks of 16 ----
    const int gwm = warp & 1, gwn = warp >> 1;
    const int rowb1 = gwm * 32, colb1 = gwn * 48;
    float acc[2][6][4];
    #pragma unroll
    for (int a = 0; a < 2; a++)
        #pragma unroll
        for (int b2 = 0; b2 < 6; b2++)
            #pragma unroll
            for (int c = 0; c < 4; c++) acc[a][b2][c] = 0.f;

    for (int kt = 0; kt < 8; kt++) {
        if (kt < 7) asm volatile("cp.async.wait_group 1;\n");
        else        asm volatile("cp.async.wait_group 0;\n");
        __syncthreads();
        const uint32_t* Bm = sB + (kt & 1) * 9216;
        #pragma unroll
        for (int kk = 0; kk < 2; kk++) {
            uint2 afp[2][2];
            #pragma unroll
            for (int mt = 0; mt < 2; mt++) {
                int row = rowb1 + mt * 16 + gid;
                int ka = kt * 16 + kk * 8 + 2 * tid4;
                afp[mt][0] = *(const uint2*)&sA[row * 136 + ka];
                afp[mt][1] = *(const uint2*)&sA[(row + 8) * 136 + ka];
            }
            uint2 bfp[6];
            #pragma unroll
            for (int nt = 0; nt < 6; nt++) {
                int n = colb1 + nt * 8 + gid;
                bfp[nt] = *(const uint2*)&Bm[n * 24 + kk * 8 + 2 * tid4];
            }
            #pragma unroll
            for (int mt = 0; mt < 2; mt++) {
                uint32_t a[4] = {afp[mt][0].x, afp[mt][1].x, afp[mt][0].y, afp[mt][1].y};
                #pragma unroll
                for (int nt = 0; nt < 6; nt++)
                    mma8(acc[mt][nt], a, (const uint32_t*)&bfp[nt]);
            }
        }
        __syncthreads();
        if (kt + 2 < 8) issueB(kt + 2, kt & 1);
    }

    // epilogue: write Q/K/V (tf32, paired) into sQ/sK/sV
    {
        const int s0 = SL(2 * tid4), s1 = SL(2 * tid4 + 1);
        #pragma unroll
        for (int mt = 0; mt < 2; mt++) {
            int r0 = rowb1 + mt * 16 + gid, r1 = r0 + 8;
            #pragma unroll
            for (int nt = 0; nt < 6; nt++) {
                int gcol = colb1 + nt * 8;
                int seg = gcol >> 7, loc = gcol & 127;
                uint32_t* dst = sm + (seg == 0 ? SQ_OFF : seg == 1 ? SK_OFF : SV_OFF) + loc;
                dst[r0 * 136 + s0] = f2tf(acc[mt][nt][0]);
                dst[r0 * 136 + s1] = f2tf(acc[mt][nt][1]);
                dst[r1 * 136 + s0] = f2tf(acc[mt][nt][2]);
                dst[r1 * 136 + s1] = f2tf(acc[mt][nt][3]);
            }
        }
    }
    __syncthreads();

    // ---- Phase B: S = Q K^T (4 warps/head, 16 q-rows each) ----
    const int head = warp >> 2;
    const int wrb = (warp & 3) * 16;
    const int hoff = head * 32;
    float sacc[8][4];
    #pragma unroll
    for (int b2 = 0; b2 < 8; b2++)
        #pragma unroll
        for (int c = 0; c < 4; c++) sacc[b2][c] = 0.f;

    #pragma unroll
    for (int kk = 0; kk < 32; kk += 8) {
        uint2 a0 = *(const uint2*)&sQ[(wrb + gid) * 136 + hoff + kk + 2 * tid4];
        uint2 a1 = *(const uint2*)&sQ[(wrb + 8 + gid) * 136 + hoff + kk + 2 * tid4];
        uint32_t a[4] = {a0.x, a1.x, a0.y, a1.y};
        #pragma unroll
        for (int nt = 0; nt < 8; nt++) {
            int key = nt * 8 + gid;
            uint2 b = *(const uint2*)&sK[key * 136 + hoff + kk + 2 * tid4];
            mma8(sacc[nt], a, (const uint32_t*)&b);
        }
    }

    // ---- Phase C: bias + masks + softmax ----
    const float scale = 0.17677669529663689f;
    const bool addUL = (wy == 15);
    const bool addLR = (wx == 15);

    #pragma unroll
    for (int rh = 0; rh < 2; rh++) {
        const int i = wrb + rh * 8 + gid;
        const int iy = i >> 3, ix = i & 7;
        float vrow[16];
        float m = -1e30f;
        #pragma unroll
        for (int nt = 0; nt < 8; nt++) {
            #pragma unroll
            for (int u = 0; u < 2; u++) {
                int j = nt * 8 + tid4 * 2 + u;
                int jy = j >> 3, jx = j & 7;
                float v = sacc[nt][rh * 2 + u] * scale
                        + sPE[(jy - iy + 7) * 15 + (jx - ix + 7)];
                if (addUL) v += ul[i * 64 + j];
                if (addLR) v += lr[i * 64 + j];
                vrow[nt * 2 + u] = v;
                m = fmaxf(m, v);
            }
        }
        m = fmaxf(m, __shfl_xor_sync(0xffffffffu, m, 1));
        m = fmaxf(m, __shfl_xor_sync(0xffffffffu, m, 2));
        float sum = 0.f;
        #pragma unroll
        for (int u2 = 0; u2 < 16; u2++) {
            vrow[u2] = __expf(vrow[u2] - m);
            sum += vrow[u2];
        }
        sum += __shfl_xor_sync(0xffffffffu, sum, 1);
        sum += __shfl_xor_sync(0xffffffffu, sum, 2);
        float inv = 1.f / sum;
        #pragma unroll
        for (int nt = 0; nt < 8; nt++) {
            #pragma unroll
            for (int u = 0; u < 2; u++)
                sacc[nt][rh * 2 + u] = vrow[nt * 2 + u] * inv;
        }
    }
    __syncthreads();   // all warps past S reads of sQ/sK

    // ---- prefetch w_outT into sW (overlays sQ+sK) ----
    #pragma unroll
    for (int jj = 0; jj < 8; jj++) {
        int i = t + 512 * jj;
        int row = i >> 5, cc = i & 31;
        CP16(saddr(sW + row * 136 + cc * 4), g_woutT + row * 128 + cc * 4);
    }
    CP_COMMIT();

    // ---- Phase D: store P (tf32, token-paired) ----
    uint32_t* myP = sP + head * (64 * 72);
    {
        const int s0 = SL(2 * tid4), s1 = SL(2 * tid4 + 1);
        #pragma unroll
        for (int rh = 0; rh < 2; rh++) {
            int i = wrb + rh * 8 + gid;
            #pragma unroll
            for (int nt = 0; nt < 8; nt++) {
                myP[i * 72 + nt * 8 + s0] = f2tf(sacc[nt][rh * 2]);
                myP[i * 72 + nt * 8 + s1] = f2tf(sacc[nt][rh * 2 + 1]);
            }
        }
    }
    __syncthreads();

    // ---- Phase E: O = P @ V ----
    float oacc[4][4];
    #pragma unroll
    for (int b2 = 0; b2 < 4; b2++)
        #pragma unroll
        for (int c = 0; c < 4; c++) oacc[b2][c] = 0.f;
    const int dslot = SL(gid);

    #pragma unroll
    for (int kk = 0; kk < 8; kk++) {
        uint2 a0 = *(const uint2*)&myP[(wrb + gid) * 72 + kk * 8 + 2 * tid4];
        uint2 a1 = *(const uint2*)&myP[(wrb + 8 + gid) * 72 + kk * 8 + 2 * tid4];
        uint32_t a[4] = {a0.x, a1.x, a0.y, a1.y};
        #pragma unroll
        for (int nt = 0; nt < 4; nt++) {
            int dcol = hoff + nt * 8 + dslot;
            uint32_t b[2];
            b[0] = sV[(kk * 8 + tid4) * 136 + dcol];
            b[1] = sV[(kk * 8 + tid4 + 4) * 136 + dcol];
            mma8(oacc[nt], a, b);
        }
    }
    __syncthreads();   // done reading sV, sP

    // ---- Phase F: store O (tf32, paired) into sO (overlays sV) ----
    {
        const int s0 = SL(2 * tid4), s1 = SL(2 * tid4 + 1);
        #pragma unroll
        for (int nt = 0; nt < 4; nt++) {
            int grp = hoff + nt * 8;
            sO[(wrb + gid) * 136 + grp + s0]     = f2tf(oacc[nt][0]);
            sO[(wrb + gid) * 136 + grp + s1]     = f2tf(oacc[nt][1]);
            sO[(wrb + 8 + gid) * 136 + grp + s0] = f2tf(oacc[nt][2]);
            sO[(wrb + 8 + gid) * 136 + grp + s1] = f2tf(oacc[nt][3]);
        }
    }
    asm volatile("cp.async.wait_group 0;\n");
    __syncthreads();

    // ---- Phase G: Y = O @ w_out + b_out, un-roll scatter ----
    const int pwm = warp & 3, pwn = warp >> 2;
    float yacc[4][4];
    #pragma unroll
    for (int b2 = 0; b2 < 4; b2++)
        #pragma unroll
        for (int c = 0; c < 4; c++) yacc[b2][c] = 0.f;

    #pragma unroll
    for (int kk = 0; kk < 16; kk++) {
        uint2 a0 = *(const uint2*)&sO[(pwm * 16 + gid) * 136 + kk * 8 + 2 * tid4];
        uint2 a1 = *(const uint2*)&sO[(pwm * 16 + 8 + gid) * 136 + kk * 8 + 2 * tid4];
        uint32_t a[4] = {a0.x, a1.x, a0.y, a1.y};
        #pragma unroll
        for (int nt = 0; nt < 4; nt++) {
            int n = pwn * 32 + nt * 8 + gid;
            uint2 b = *(const uint2*)&sW[n * 136 + kk * 8 + 2 * tid4];
            mma8(yacc[nt], a, (const uint32_t*)&b);
        }
    }

    #pragma unroll
    for (int rh = 0; rh < 2; rh++) {
        int i = pwm * 16 + rh * 8 + gid;
        int ty = i >> 3, tx = i & 7;
        int h = (wy * 8 + ty + 4) & 127;
        int w = (wx * 8 + tx + 4) & 127;
        float* orow = out + (((size_t)bb * 128 + h) * 128 + w) * 128;
        #pragma unroll
        for (int nt = 0; nt < 4; nt++) {
            int c = pwn * 32 + nt * 8 + tid4 * 2;
            float2 v = make_float2(yacc[nt][rh * 2]     + sBO[c],
                                   yacc[nt][rh * 2 + 1] + sBO[c + 1]);
            *(float2*)(orow + c) = v;
        }
    }
}

// ===========================================================================
extern "C" void kernel_launch(void* const* d_in, const int* in_sizes, int n_in,
                              void* d_out, int out_size) {
    const float* x    = (const float*)d_in[0];
    const float* wqkv = (const float*)d_in[1];
    const float* wout = (const float*)d_in[2];
    const float* bout = (const float*)d_in[3];
    const float* pe   = (const float*)d_in[4];
    const float* ul   = (const float*)d_in[5];
    const float* lr   = (const float*)d_in[6];
    float* out = (float*)d_out;

    cudaFuncSetAttribute(fused_kernel, cudaFuncAttributeMaxDynamicSharedMemorySize, FU_SMEM);

    cvt_kernel<<<192, 256>>>(wqkv, wout);
    fused_kernel<<<4096, 512, FU_SMEM>>>(x, bout, pe, ul, lr, out);
}